// round 14
// baseline (speedup 1.0000x reference)
#include <cuda_runtime.h>
#include <cstdint>
#include <cstddef>

// ---------------- problem constants ----------------
#define BB 256
#define LL 512
#define VV 64
#define HH 256
#define DD 32768               // LL*VV
#define MAXR 15
#define TINYF 1.1754943508222875e-38f

// ---------------- scratch (device globals; no allocations) ----------------
__device__ float d_gx[BB * DD];        // grad wrt x (B,D)
__device__ float d_gy[BB * DD];        // grad wrt y
__device__ float d_gvx[BB * HH];
__device__ float d_gvy[BB * HH];
__device__ float d_scx[BB];
__device__ float d_scy[BB];
__device__ float d_Sx[BB * LL];        // sum_v exp(g/2) per (b,l)
__device__ float d_Sy[BB * LL];
__device__ int   d_lab0[BB * LL];
__device__ int   d_ylab[BB * LL];
__device__ float d_M[MAXR * BB * LL];  // per-step per-position group max of g/2+z
__device__ unsigned char d_A[MAXR * BB * LL]; // argmax v within group
__device__ int   d_idx[BB * MAXR];
__device__ float d_logfwd[BB];
__device__ int   d_accept[BB];

struct KeyBlob { uint32_t k0[MAXR]; uint32_t k1[MAXR]; };

// ---------------- threefry2x32 (exact JAX schedule) ----------------
__device__ __forceinline__ void tf2x32(uint32_t k0, uint32_t k1,
                                       uint32_t x0, uint32_t x1,
                                       uint32_t& o0, uint32_t& o1) {
    uint32_t k2 = k0 ^ k1 ^ 0x1BD11BDAu;
    x0 += k0; x1 += k1;
#define TFR(r) { x0 += x1; x1 = __funnelshift_l(x1, x1, r); x1 ^= x0; }
    TFR(13) TFR(15) TFR(26) TFR(6)   x0 += k1; x1 += k2 + 1u;
    TFR(17) TFR(29) TFR(16) TFR(24)  x0 += k2; x1 += k0 + 2u;
    TFR(13) TFR(15) TFR(26) TFR(6)   x0 += k0; x1 += k1 + 3u;
    TFR(17) TFR(29) TFR(16) TFR(24)  x0 += k1; x1 += k2 + 4u;
    TFR(13) TFR(15) TFR(26) TFR(6)   x0 += k2; x1 += k0 + 5u;
#undef TFR
    o0 = x0; o1 = x1;
}

static void h_tf2x32(uint32_t k0, uint32_t k1, uint32_t x0, uint32_t x1,
                     uint32_t* o0, uint32_t* o1) {
    uint32_t k2 = k0 ^ k1 ^ 0x1BD11BDAu;
    x0 += k0; x1 += k1;
#define HTR(r) { x0 += x1; x1 = (x1 << r) | (x1 >> (32 - r)); x1 ^= x0; }
    HTR(13) HTR(15) HTR(26) HTR(6)   x0 += k1; x1 += k2 + 1u;
    HTR(17) HTR(29) HTR(16) HTR(24)  x0 += k2; x1 += k0 + 2u;
    HTR(13) HTR(15) HTR(26) HTR(6)   x0 += k0; x1 += k1 + 3u;
    HTR(17) HTR(29) HTR(16) HTR(24)  x0 += k1; x1 += k2 + 4u;
    HTR(13) HTR(15) HTR(26) HTR(6)   x0 += k2; x1 += k0 + 5u;
#undef HTR
    *o0 = x0; *o1 = x1;
}

// gumbel exactly as JAX: uniform(key, minval=tiny, maxval=1) then -log(-log(u))
__device__ __forceinline__ float gumbel_from_bits(uint32_t bits) {
    float u = __uint_as_float((bits >> 9) | 0x3f800000u) - 1.0f;
    u = fmaxf(TINYF, u + TINYF);
    return -logf(-logf(u));
}

// order-preserving uint from float (no NaNs in our data)
__device__ __forceinline__ uint32_t ordf(float v) {
    uint32_t b = __float_as_uint(v);
    return (b & 0x80000000u) ? ~b : (b | 0x80000000u);
}
__device__ __forceinline__ float unordf(uint32_t b) {
    return __uint_as_float((b & 0x80000000u) ? (b ^ 0x80000000u) : ~b);
}

// ---------------- kernels ----------------

// labels from one-hot x
__global__ void k_decode(const float* __restrict__ x) {
    int i = blockIdx.x * blockDim.x + threadIdx.x;
    if (i >= BB * LL) return;
    const float* row = x + (size_t)i * VV;
    int best = 0; float bv = row[0];
    for (int v = 1; v < VV; v++) { float f = row[v]; if (f > bv) { bv = f; best = v; } }
    d_lab0[i] = best;
}

// a[b,h] = sum_l W1[l*V+lab, h]; gv = w2*(1-tanh^2); score = tanh(a).w2
__global__ void k_embed(const float* __restrict__ W1, const float* __restrict__ w2, int pass) {
    const int* lab = pass ? d_ylab : d_lab0;
    float* gv      = pass ? d_gvy  : d_gvx;
    float* score   = pass ? d_scy  : d_scx;
    int b = blockIdx.x, h = threadIdx.x;            // 256 threads
    __shared__ int labs[LL];
    for (int l = h; l < LL; l += 256) labs[l] = lab[b * LL + l];
    __syncthreads();
    float acc = 0.f;
#pragma unroll 4
    for (int l = 0; l < LL; l++) {
        int r = l * VV + labs[l];
        acc += W1[(size_t)r * HH + h];
    }
    float ht = tanhf(acc);
    float w  = w2[h];
    gv[b * HH + h] = w * (1.f - ht * ht);
    float s = ht * w;
    __shared__ float red[8];
    for (int off = 16; off; off >>= 1) s += __shfl_xor_sync(0xffffffffu, s, off);
    if ((h & 31) == 0) red[h >> 5] = s;
    __syncthreads();
    if (h < 8) {
        float t = red[h];
        for (int off = 4; off; off >>= 1) t += __shfl_xor_sync(0xffu, t, off);
        if (h == 0) score[b] = t;
    }
}

// grad[b,d] = sum_h W1[d,h]*gv[b,h]  — tiled fp32 GEMM (64x64 tiles, 4x4 micro)
__global__ void k_gemm(const float* __restrict__ W1, int pass) {
    const float* gv = pass ? d_gvy : d_gvx;
    float* g        = pass ? d_gy  : d_gx;
    __shared__ float ws[16][64];
    __shared__ float as[16][64];
    int tid = threadIdx.x;
    int tx = tid & 15, ty = tid >> 4;
    int d0 = blockIdx.x * 64, b0 = blockIdx.y * 64;
    int ld = tid & 63;
    int lk = (tid >> 6) << 2;
    float acc[4][4];
#pragma unroll
    for (int i = 0; i < 4; i++)
#pragma unroll
        for (int j = 0; j < 4; j++) acc[i][j] = 0.f;

    for (int kk0 = 0; kk0 < HH; kk0 += 16) {
        float4 wv = *(const float4*)&W1[(size_t)(d0 + ld) * HH + kk0 + lk];
        float4 av = *(const float4*)&gv[(size_t)(b0 + ld) * HH + kk0 + lk];
        ws[lk + 0][ld] = wv.x; ws[lk + 1][ld] = wv.y; ws[lk + 2][ld] = wv.z; ws[lk + 3][ld] = wv.w;
        as[lk + 0][ld] = av.x; as[lk + 1][ld] = av.y; as[lk + 2][ld] = av.z; as[lk + 3][ld] = av.w;
        __syncthreads();
#pragma unroll
        for (int kk = 0; kk < 16; kk++) {
            float4 w4 = *(const float4*)&ws[kk][tx * 4];
            float4 a4 = *(const float4*)&as[kk][ty * 4];
            float wr[4] = { w4.x, w4.y, w4.z, w4.w };
            float ar[4] = { a4.x, a4.y, a4.z, a4.w };
#pragma unroll
            for (int i = 0; i < 4; i++)
#pragma unroll
                for (int j = 0; j < 4; j++) acc[i][j] = fmaf(ar[i], wr[j], acc[i][j]);
        }
        __syncthreads();
    }
#pragma unroll
    for (int i = 0; i < 4; i++) {
        float4 o = { acc[i][0], acc[i][1], acc[i][2], acc[i][3] };
        *(float4*)&g[(size_t)(b0 + ty * 4 + i) * DD + d0 + tx * 4] = o;
    }
}

// S[b,l] = sum_v exp(g/2)
__global__ void k_S(int pass) {
    const float* g = pass ? d_gy : d_gx;
    float* S       = pass ? d_Sy : d_Sx;
    int i = blockIdx.x * blockDim.x + threadIdx.x;
    if (i >= BB * LL) return;
    const float4* p = (const float4*)(g + (size_t)i * VV);
    float s = 0.f;
#pragma unroll
    for (int q = 0; q < 16; q++) {
        float4 f = p[q];
        s += expf(0.5f * f.x) + expf(0.5f * f.y) + expf(0.5f * f.z) + expf(0.5f * f.w);
    }
    S[i] = s;
}

// heavy: per step t, per (b,l): M = max_v(g/2 + gumbel), A = first argmax v.
// PARTITIONABLE threefry: per-element u64 counter i -> tf(key, hi32(i)=0, lo32(i)),
// 32-bit output = o0 ^ o1. One warp per (b,l); lane handles v=lane, v=lane+32.
__global__ void k_gumbel(KeyBlob kb) {
    int w = (blockIdx.x * blockDim.x + threadIdx.x) >> 5;
    int lane = threadIdx.x & 31;
    if (w >= BB * LL) return;
    int b = w >> 9, l = w & 511;
    size_t base = (size_t)b * DD + (size_t)l * VV;
    float g0 = d_gx[base + lane] * 0.5f;
    float g1 = d_gx[base + lane + 32] * 0.5f;
    uint32_t c0 = (uint32_t)b * DD + (uint32_t)l * VV + (uint32_t)lane;   // < 2^23, hi32 = 0
    uint32_t c1 = c0 + 32u;

    for (int t = 0; t < MAXR; t++) {
        uint32_t k0 = kb.k0[t], k1 = kb.k1[t];
        uint32_t a0, a1, e0, e1;
        tf2x32(k0, k1, 0u, c0, a0, a1);
        tf2x32(k0, k1, 0u, c1, e0, e1);
        float z0 = g0 + gumbel_from_bits(a0 ^ a1);
        float z1 = g1 + gumbel_from_bits(e0 ^ e1);

        // pack (value, first-index tie-break): larger key wins; (63-idx) in low bits
        unsigned long long key  = ((unsigned long long)ordf(z0) << 6) | (unsigned)(63 - lane);
        unsigned long long keyb = ((unsigned long long)ordf(z1) << 6) | (unsigned)(63 - (lane + 32));
        if (keyb > key) key = keyb;

        for (int off = 16; off; off >>= 1) {
            unsigned long long o = __shfl_xor_sync(0xffffffffu, key, off);
            if (o > key) key = o;
        }
        if (lane == 0) {
            size_t mo = ((size_t)t * BB + b) * LL + l;
            d_M[mo] = unordf((uint32_t)(key >> 6));
            d_A[mo] = (unsigned char)(63 - (int)(key & 63));
        }
    }
}

// forward scan: per batch, 15 sequential steps; 512 threads, thread l owns position l
__global__ void k_scan(const int* __restrict__ radius) {
    int b = blockIdx.x, l = threadIdx.x;
    int cur  = d_lab0[b * LL + l];
    float cx = d_gx[(size_t)b * DD + l * VV + cur];
    float Sl = d_Sx[b * LL + l];
    int rad  = radius[b];
    __shared__ float s_red[16];
    __shared__ unsigned long long s_key[16];
    __shared__ float s_T;
    __shared__ float s_lf;
    __shared__ int s_win;
    if (l == 0) s_lf = 0.f;
    __syncthreads();
    for (int t = 0; t < MAXR; t++) {
        float val = d_M[((size_t)t * BB + b) * LL + l] - 0.5f * cx;
        unsigned long long key = (((unsigned long long)ordf(val)) << 9) | (unsigned)(511 - l);
        float e = expf(-0.5f * cx) * Sl;
        for (int off = 16; off; off >>= 1) {
            unsigned long long ok = __shfl_xor_sync(0xffffffffu, key, off);
            if (ok > key) key = ok;
            e += __shfl_xor_sync(0xffffffffu, e, off);
        }
        int wid = l >> 5, ln = l & 31;
        if (ln == 0) { s_key[wid] = key; s_red[wid] = e; }
        __syncthreads();
        if (l < 16) {
            unsigned long long k2 = s_key[l]; float e2 = s_red[l];
            for (int off = 8; off; off >>= 1) {
                unsigned long long ok = __shfl_xor_sync(0xffffu, k2, off);
                if (ok > k2) k2 = ok;
                e2 += __shfl_xor_sync(0xffffu, e2, off);
            }
            if (l == 0) { s_T = e2; s_win = 511 - (int)(k2 & 511); }
        }
        __syncthreads();
        int lw = s_win;
        if (l == lw) {
            int v = (int)d_A[((size_t)t * BB + b) * LL + l];
            int idx = l * VV + v;
            d_idx[b * MAXR + t] = idx;
            float gval = d_gx[(size_t)b * DD + idx];
            float term = (gval - cx) * 0.5f - logf(s_T);
            if (t < rad) {
                s_lf += term;
                cur = v; cx = gval;
            }
        }
        __syncthreads();
    }
    d_ylab[b * LL + l] = cur;
    if (l == 0) d_logfwd[b] = s_lf + d_scx[b];
}

// backward logp + acceptance (partitionable uniform: counter (0,b), xor fold)
__global__ void k_back(const int* __restrict__ radius, uint32_t uk0, uint32_t uk1) {
    int b = blockIdx.x, l = threadIdx.x;
    int cur  = d_lab0[b * LL + l];
    float cy = d_gy[(size_t)b * DD + l * VV + cur];
    float Sl = d_Sy[b * LL + l];
    int rad  = radius[b];
    __shared__ float s_red[16];
    __shared__ float s_T;
    __shared__ float s_lb;
    if (l == 0) s_lb = 0.f;
    __syncthreads();
    for (int t = 0; t < MAXR; t++) {
        int idx = d_idx[b * MAXR + t];
        int lw = idx >> 6, vw = idx & 63;
        if (t < rad && l == lw) { cur = vw; cy = d_gy[(size_t)b * DD + idx]; }
        float e = expf(-0.5f * cy) * Sl;
        for (int off = 16; off; off >>= 1) e += __shfl_xor_sync(0xffffffffu, e, off);
        int wid = l >> 5, ln = l & 31;
        if (ln == 0) s_red[wid] = e;
        __syncthreads();
        if (l < 16) {
            float e2 = s_red[l];
            for (int off = 8; off; off >>= 1) e2 += __shfl_xor_sync(0xffffu, e2, off);
            if (l == 0) s_T = e2;
        }
        __syncthreads();
        if (l == lw) {
            float gval = d_gy[(size_t)b * DD + idx];
            float term = (gval - cy) * 0.5f - logf(s_T);
            s_lb += term;
        }
        __syncthreads();
    }
    if (l == 0) {
        float lacc = (s_lb + d_scy[b]) - d_logfwd[b];
        uint32_t o0, o1;
        tf2x32(uk0, uk1, 0u, (uint32_t)b, o0, o1);
        uint32_t bits = o0 ^ o1;
        float u = __uint_as_float((bits >> 9) | 0x3f800000u) - 1.0f;
        d_accept[b] = (expf(lacc) >= u) ? 1 : 0;
    }
}

// out[b,l,:] = onehot(accepted ? ylab : lab0)
__global__ void k_out(float* __restrict__ out) {
    int i = blockIdx.x * blockDim.x + threadIdx.x;
    if (i >= BB * LL) return;
    int b = i / LL;
    int c = d_accept[b] ? d_ylab[i] : d_lab0[i];
    float4* p = (float4*)(out + (size_t)i * VV);
    float4 z = { 0.f, 0.f, 0.f, 0.f };
#pragma unroll
    for (int q = 0; q < 16; q++) p[q] = z;
    out[(size_t)i * VV + c] = 1.0f;
}

// ---------------- launch ----------------
extern "C" void kernel_launch(void* const* d_in, const int* in_sizes, int n_in,
                              void* d_out, int out_size) {
    (void)in_sizes; (void)n_in; (void)out_size;
    const float* x      = (const float*)d_in[0];
    const float* W1     = (const float*)d_in[1];
    const float* w2     = (const float*)d_in[2];
    const int*   radius = (const int*)  d_in[3];
    float* out = (float*)d_out;

    // keys = jax.random.split(jax.random.key(1), 15) with threefry_partitionable:
    // child key t = full threefry output pair with counter (hi=0, lo=t), key data (0,1).
    KeyBlob kb;
    for (int t = 0; t < MAXR; t++)
        h_tf2x32(0u, 1u, 0u, (uint32_t)t, &kb.k0[t], &kb.k1[t]);

    k_decode<<<(BB * LL + 255) / 256, 256>>>(x);
    k_embed<<<BB, 256>>>(W1, w2, 0);
    k_gemm<<<dim3(DD / 64, BB / 64), 256>>>(W1, 0);
    k_S<<<(BB * LL + 255) / 256, 256>>>(0);
    k_gumbel<<<(BB * LL) / 8, 256>>>(kb);           // 8 warps/block, one warp per (b,l)
    k_scan<<<BB, LL>>>(radius);
    k_embed<<<BB, 256>>>(W1, w2, 1);
    k_gemm<<<dim3(DD / 64, BB / 64), 256>>>(W1, 1);
    k_S<<<(BB * LL + 255) / 256, 256>>>(1);
    k_back<<<BB, LL>>>(radius, 0u, 2u);             // key(2) data = (0,2)
    k_out<<<(BB * LL + 255) / 256, 256>>>(out);
}

// round 17
// speedup vs baseline: 1.1259x; 1.1259x over previous
#include <cuda_runtime.h>
#include <cstdint>
#include <cstddef>

// ---------------- problem constants ----------------
#define BB 256
#define LL 512
#define VV 64
#define HH 256
#define DD 32768               // LL*VV
#define MAXR 15
#define TINYF 1.1754943508222875e-38f

// ---------------- scratch (device globals; no allocations) ----------------
__device__ float d_gx[BB * DD];        // grad wrt x (B,D)
__device__ float d_gy[BB * DD];        // grad wrt y
__device__ float d_gvx[BB * HH];
__device__ float d_gvy[BB * HH];
__device__ float d_scx[BB];
__device__ float d_scy[BB];
__device__ float d_Sx[BB * LL];        // sum_v exp(g/2) per (b,l)
__device__ float d_Sy[BB * LL];
__device__ int   d_lab0[BB * LL];
__device__ int   d_ylab[BB * LL];
__device__ float d_M[MAXR * BB * LL];  // per-step per-(b,l): max_v e^{g/2}/(-log u)  (ratio form)
__device__ unsigned char d_A[MAXR * BB * LL]; // argmax v within group
__device__ int   d_idx[BB * MAXR];
__device__ float d_logfwd[BB];
__device__ int   d_accept[BB];

struct KeyBlob { uint32_t k0[MAXR]; uint32_t k1[MAXR]; };

// ---------------- threefry2x32 (exact JAX schedule) ----------------
__device__ __forceinline__ void tf2x32(uint32_t k0, uint32_t k1,
                                       uint32_t x0, uint32_t x1,
                                       uint32_t& o0, uint32_t& o1) {
    uint32_t k2 = k0 ^ k1 ^ 0x1BD11BDAu;
    x0 += k0; x1 += k1;
#define TFR(r) { x0 += x1; x1 = __funnelshift_l(x1, x1, r); x1 ^= x0; }
    TFR(13) TFR(15) TFR(26) TFR(6)   x0 += k1; x1 += k2 + 1u;
    TFR(17) TFR(29) TFR(16) TFR(24)  x0 += k2; x1 += k0 + 2u;
    TFR(13) TFR(15) TFR(26) TFR(6)   x0 += k0; x1 += k1 + 3u;
    TFR(17) TFR(29) TFR(16) TFR(24)  x0 += k1; x1 += k2 + 4u;
    TFR(13) TFR(15) TFR(26) TFR(6)   x0 += k2; x1 += k0 + 5u;
#undef TFR
    o0 = x0; o1 = x1;
}

static void h_tf2x32(uint32_t k0, uint32_t k1, uint32_t x0, uint32_t x1,
                     uint32_t* o0, uint32_t* o1) {
    uint32_t k2 = k0 ^ k1 ^ 0x1BD11BDAu;
    x0 += k0; x1 += k1;
#define HTR(r) { x0 += x1; x1 = (x1 << r) | (x1 >> (32 - r)); x1 ^= x0; }
    HTR(13) HTR(15) HTR(26) HTR(6)   x0 += k1; x1 += k2 + 1u;
    HTR(17) HTR(29) HTR(16) HTR(24)  x0 += k2; x1 += k0 + 2u;
    HTR(13) HTR(15) HTR(26) HTR(6)   x0 += k0; x1 += k1 + 3u;
    HTR(17) HTR(29) HTR(16) HTR(24)  x0 += k1; x1 += k2 + 4u;
    HTR(13) HTR(15) HTR(26) HTR(6)   x0 += k2; x1 += k0 + 5u;
#undef HTR
    *o0 = x0; *o1 = x1;
}

// uniform exactly as JAX: bits -> [1,2) -> -1 -> clamp to [tiny, 1)
__device__ __forceinline__ float unif_from_bits(uint32_t bits) {
    float u = __uint_as_float((bits >> 9) | 0x3f800000u) - 1.0f;
    return fmaxf(TINYF, u + TINYF);
}

// order-preserving uint from float (no NaNs in our data)
__device__ __forceinline__ uint32_t ordf(float v) {
    uint32_t b = __float_as_uint(v);
    return (b & 0x80000000u) ? ~b : (b | 0x80000000u);
}
__device__ __forceinline__ float unordf(uint32_t b) {
    return __uint_as_float((b & 0x80000000u) ? (b ^ 0x80000000u) : ~b);
}

// ---------------- kernels ----------------

// labels from one-hot x
__global__ void k_decode(const float* __restrict__ x) {
    int i = blockIdx.x * blockDim.x + threadIdx.x;
    if (i >= BB * LL) return;
    const float* row = x + (size_t)i * VV;
    int best = 0; float bv = row[0];
    for (int v = 1; v < VV; v++) { float f = row[v]; if (f > bv) { bv = f; best = v; } }
    d_lab0[i] = best;
}

// a[b,h] = sum_l W1[l*V+lab, h]; gv = w2*(1-tanh^2); score = tanh(a).w2
__global__ void k_embed(const float* __restrict__ W1, const float* __restrict__ w2, int pass) {
    const int* lab = pass ? d_ylab : d_lab0;
    float* gv      = pass ? d_gvy  : d_gvx;
    float* score   = pass ? d_scy  : d_scx;
    int b = blockIdx.x, h = threadIdx.x;            // 256 threads
    __shared__ int labs[LL];
    for (int l = h; l < LL; l += 256) labs[l] = lab[b * LL + l];
    __syncthreads();
    float acc = 0.f;
#pragma unroll 4
    for (int l = 0; l < LL; l++) {
        int r = l * VV + labs[l];
        acc += W1[(size_t)r * HH + h];
    }
    float ht = tanhf(acc);
    float w  = w2[h];
    gv[b * HH + h] = w * (1.f - ht * ht);
    float s = ht * w;
    __shared__ float red[8];
    for (int off = 16; off; off >>= 1) s += __shfl_xor_sync(0xffffffffu, s, off);
    if ((h & 31) == 0) red[h >> 5] = s;
    __syncthreads();
    if (h < 8) {
        float t = red[h];
        for (int off = 4; off; off >>= 1) t += __shfl_xor_sync(0xffu, t, off);
        if (h == 0) score[b] = t;
    }
}

// grad[b,d] = sum_h W1[d,h]*gv[b,h]
// 128(d) x 128(b) tile, 256 threads, 8x8 micro-tile, K-chunk 8
__global__ void __launch_bounds__(256, 2) k_gemm(const float* __restrict__ W1, int pass) {
    const float* gv = pass ? d_gvy : d_gvx;
    float* g        = pass ? d_gy  : d_gx;
    __shared__ float ws[8][132];   // [k][d] padded
    __shared__ float as[8][132];   // [k][b] padded
    int tid = threadIdx.x;
    int tx = tid & 15, ty = tid >> 4;          // tx -> d micro, ty -> b micro
    int d0 = blockIdx.x * 128, b0 = blockIdx.y * 128;
    int lrow = tid >> 1;                        // 0..127
    int lk   = (tid & 1) * 4;                   // 0 or 4

    float acc[8][8];
#pragma unroll
    for (int i = 0; i < 8; i++)
#pragma unroll
        for (int j = 0; j < 8; j++) acc[i][j] = 0.f;

    for (int kc = 0; kc < HH; kc += 8) {
        float4 wv = *(const float4*)&W1[(size_t)(d0 + lrow) * HH + kc + lk];
        float4 av = *(const float4*)&gv[(size_t)(b0 + lrow) * HH + kc + lk];
        __syncthreads();
        ws[lk + 0][lrow] = wv.x; ws[lk + 1][lrow] = wv.y;
        ws[lk + 2][lrow] = wv.z; ws[lk + 3][lrow] = wv.w;
        as[lk + 0][lrow] = av.x; as[lk + 1][lrow] = av.y;
        as[lk + 2][lrow] = av.z; as[lk + 3][lrow] = av.w;
        __syncthreads();
#pragma unroll
        for (int kk = 0; kk < 8; kk++) {
            float4 w0 = *(const float4*)&ws[kk][tx * 8];
            float4 w1 = *(const float4*)&ws[kk][tx * 8 + 4];
            float4 a0 = *(const float4*)&as[kk][ty * 8];
            float4 a1 = *(const float4*)&as[kk][ty * 8 + 4];
            float wr[8] = { w0.x, w0.y, w0.z, w0.w, w1.x, w1.y, w1.z, w1.w };
            float ar[8] = { a0.x, a0.y, a0.z, a0.w, a1.x, a1.y, a1.z, a1.w };
#pragma unroll
            for (int i = 0; i < 8; i++)
#pragma unroll
                for (int j = 0; j < 8; j++) acc[i][j] = fmaf(ar[i], wr[j], acc[i][j]);
        }
    }
#pragma unroll
    for (int i = 0; i < 8; i++) {
        size_t row = (size_t)(b0 + ty * 8 + i) * DD + d0 + tx * 8;
        float4 o0 = { acc[i][0], acc[i][1], acc[i][2], acc[i][3] };
        float4 o1 = { acc[i][4], acc[i][5], acc[i][6], acc[i][7] };
        *(float4*)&g[row]     = o0;
        *(float4*)&g[row + 4] = o1;
    }
}

// S[b,l] = sum_v exp(g/2)   (only needed for the y pass; x pass fused into k_gumbel)
__global__ void k_S(int pass) {
    const float* g = pass ? d_gy : d_gx;
    float* S       = pass ? d_Sy : d_Sx;
    int i = blockIdx.x * blockDim.x + threadIdx.x;
    if (i >= BB * LL) return;
    const float4* p = (const float4*)(g + (size_t)i * VV);
    float s = 0.f;
#pragma unroll
    for (int q = 0; q < 16; q++) {
        float4 f = p[q];
        s += expf(0.5f * f.x) + expf(0.5f * f.y) + expf(0.5f * f.z) + expf(0.5f * f.w);
    }
    S[i] = s;
}

// heavy: per step t, per (b,l): ratio-form gumbel argmax.
//   argmax_v (g/2 - log(-log u))  ==  argmax_v  e^{g/2} / (-log u)
// e^{g/2} is hoisted out of the 15-step loop (2 expf per lane total).
// Per draw: 1 threefry + 1 precise logf + 1 fast divide.
// Also fuses S-x: d_Sx[b,l] = sum_v e^{g/2}.
__global__ void k_gumbel(KeyBlob kb) {
    int w = (blockIdx.x * blockDim.x + threadIdx.x) >> 5;
    int lane = threadIdx.x & 31;
    if (w >= BB * LL) return;
    int b = w >> 9, l = w & 511;
    size_t base = (size_t)b * DD + (size_t)l * VV;
    float eg0 = expf(0.5f * d_gx[base + lane]);
    float eg1 = expf(0.5f * d_gx[base + lane + 32]);
    // fused S-x (robust path: enters only logp)
    float s = eg0 + eg1;
    for (int off = 16; off; off >>= 1) s += __shfl_xor_sync(0xffffffffu, s, off);
    if (lane == 0) d_Sx[b * LL + l] = s;

    uint32_t c0 = (uint32_t)b * DD + (uint32_t)l * VV + (uint32_t)lane;   // < 2^23, hi32 = 0
    uint32_t c1 = c0 + 32u;

    for (int t = 0; t < MAXR; t++) {
        uint32_t k0 = kb.k0[t], k1 = kb.k1[t];
        uint32_t a0, a1, e0, e1;
        tf2x32(k0, k1, 0u, c0, a0, a1);
        tf2x32(k0, k1, 0u, c1, e0, e1);
        float w0 = -logf(unif_from_bits(a0 ^ a1));       // -log u  in (1.19e-7, 87.4]
        float w1 = -logf(unif_from_bits(e0 ^ e1));
        float r0 = __fdividef(eg0, w0);                  // in [~0.006, ~1.8e7]
        float r1 = __fdividef(eg1, w1);

        // pack (value, first-index tie-break): larger key wins; (63-idx) in low bits
        unsigned long long key  = ((unsigned long long)ordf(r0) << 6) | (unsigned)(63 - lane);
        unsigned long long keyb = ((unsigned long long)ordf(r1) << 6) | (unsigned)(63 - (lane + 32));
        if (keyb > key) key = keyb;

        for (int off = 16; off; off >>= 1) {
            unsigned long long o = __shfl_xor_sync(0xffffffffu, key, off);
            if (o > key) key = o;
        }
        if (lane == 0) {
            size_t mo = ((size_t)t * BB + b) * LL + l;
            d_M[mo] = unordf((uint32_t)(key >> 6));      // ratio max (positive float)
            d_A[mo] = (unsigned char)(63 - (int)(key & 63));
        }
    }
}

// forward scan: per batch, 15 sequential steps; 512 threads, thread l owns position l.
// cross-l selection uses val = R_l * e^{-cx_l/2}  (monotone image of M_l - cx_l/2).
__global__ void k_scan(const int* __restrict__ radius) {
    int b = blockIdx.x, l = threadIdx.x;
    int cur  = d_lab0[b * LL + l];
    float cx = d_gx[(size_t)b * DD + l * VV + cur];
    float Sl = d_Sx[b * LL + l];
    int rad  = radius[b];
    __shared__ float s_red[16];
    __shared__ unsigned long long s_key[16];
    __shared__ float s_T;
    __shared__ float s_lf;
    __shared__ int s_win;
    if (l == 0) s_lf = 0.f;
    __syncthreads();
    for (int t = 0; t < MAXR; t++) {
        float ecx = expf(-0.5f * cx);
        float val = d_M[((size_t)t * BB + b) * LL + l] * ecx;
        unsigned long long key = (((unsigned long long)ordf(val)) << 9) | (unsigned)(511 - l);
        float e = ecx * Sl;
        for (int off = 16; off; off >>= 1) {
            unsigned long long ok = __shfl_xor_sync(0xffffffffu, key, off);
            if (ok > key) key = ok;
            e += __shfl_xor_sync(0xffffffffu, e, off);
        }
        int wid = l >> 5, ln = l & 31;
        if (ln == 0) { s_key[wid] = key; s_red[wid] = e; }
        __syncthreads();
        if (l < 16) {
            unsigned long long k2 = s_key[l]; float e2 = s_red[l];
            for (int off = 8; off; off >>= 1) {
                unsigned long long ok = __shfl_xor_sync(0xffffu, k2, off);
                if (ok > k2) k2 = ok;
                e2 += __shfl_xor_sync(0xffffu, e2, off);
            }
            if (l == 0) { s_T = e2; s_win = 511 - (int)(k2 & 511); }
        }
        __syncthreads();
        int lw = s_win;
        if (l == lw) {
            int v = (int)d_A[((size_t)t * BB + b) * LL + l];
            int idx = l * VV + v;
            d_idx[b * MAXR + t] = idx;
            float gval = d_gx[(size_t)b * DD + idx];
            float term = (gval - cx) * 0.5f - logf(s_T);
            if (t < rad) {
                s_lf += term;
                cur = v; cx = gval;
            }
        }
        __syncthreads();
    }
    d_ylab[b * LL + l] = cur;
    if (l == 0) d_logfwd[b] = s_lf + d_scx[b];
}

// backward logp + acceptance (partitionable uniform: counter (0,b), xor fold)
__global__ void k_back(const int* __restrict__ radius, uint32_t uk0, uint32_t uk1) {
    int b = blockIdx.x, l = threadIdx.x;
    int cur  = d_lab0[b * LL + l];
    float cy = d_gy[(size_t)b * DD + l * VV + cur];
    float Sl = d_Sy[b * LL + l];
    int rad  = radius[b];
    __shared__ float s_red[16];
    __shared__ float s_T;
    __shared__ float s_lb;
    if (l == 0) s_lb = 0.f;
    __syncthreads();
    for (int t = 0; t < MAXR; t++) {
        int idx = d_idx[b * MAXR + t];
        int lw = idx >> 6, vw = idx & 63;
        if (t < rad && l == lw) { cur = vw; cy = d_gy[(size_t)b * DD + idx]; }
        float e = expf(-0.5f * cy) * Sl;
        for (int off = 16; off; off >>= 1) e += __shfl_xor_sync(0xffffffffu, e, off);
        int wid = l >> 5, ln = l & 31;
        if (ln == 0) s_red[wid] = e;
        __syncthreads();
        if (l < 16) {
            float e2 = s_red[l];
            for (int off = 8; off; off >>= 1) e2 += __shfl_xor_sync(0xffffu, e2, off);
            if (l == 0) s_T = e2;
        }
        __syncthreads();
        if (l == lw) {
            float gval = d_gy[(size_t)b * DD + idx];
            float term = (gval - cy) * 0.5f - logf(s_T);
            s_lb += term;
        }
        __syncthreads();
    }
    if (l == 0) {
        float lacc = (s_lb + d_scy[b]) - d_logfwd[b];
        uint32_t o0, o1;
        tf2x32(uk0, uk1, 0u, (uint32_t)b, o0, o1);
        uint32_t bits = o0 ^ o1;
        float u = __uint_as_float((bits >> 9) | 0x3f800000u) - 1.0f;
        d_accept[b] = (expf(lacc) >= u) ? 1 : 0;
    }
}

// out[b,l,:] = onehot(accepted ? ylab : lab0)
__global__ void k_out(float* __restrict__ out) {
    int i = blockIdx.x * blockDim.x + threadIdx.x;
    if (i >= BB * LL) return;
    int b = i / LL;
    int c = d_accept[b] ? d_ylab[i] : d_lab0[i];
    float4* p = (float4*)(out + (size_t)i * VV);
    float4 z = { 0.f, 0.f, 0.f, 0.f };
#pragma unroll
    for (int q = 0; q < 16; q++) p[q] = z;
    out[(size_t)i * VV + c] = 1.0f;
}

// ---------------- launch ----------------
extern "C" void kernel_launch(void* const* d_in, const int* in_sizes, int n_in,
                              void* d_out, int out_size) {
    (void)in_sizes; (void)n_in; (void)out_size;
    const float* x      = (const float*)d_in[0];
    const float* W1     = (const float*)d_in[1];
    const float* w2     = (const float*)d_in[2];
    const int*   radius = (const int*)  d_in[3];
    float* out = (float*)d_out;

    // keys = jax.random.split(jax.random.key(1), 15) with threefry_partitionable:
    // child key t = full threefry output pair with counter (hi=0, lo=t), key data (0,1).
    KeyBlob kb;
    for (int t = 0; t < MAXR; t++)
        h_tf2x32(0u, 1u, 0u, (uint32_t)t, &kb.k0[t], &kb.k1[t]);

    k_decode<<<(BB * LL + 255) / 256, 256>>>(x);
    k_embed<<<BB, 256>>>(W1, w2, 0);
    k_gemm<<<dim3(DD / 128, BB / 128), 256>>>(W1, 0);
    k_gumbel<<<(BB * LL) / 8, 256>>>(kb);           // 8 warps/block, one warp per (b,l); writes d_Sx
    k_scan<<<BB, LL>>>(radius);
    k_embed<<<BB, 256>>>(W1, w2, 1);
    k_gemm<<<dim3(DD / 128, BB / 128), 256>>>(W1, 1);
    k_S<<<(BB * LL + 255) / 256, 256>>>(1);
    k_back<<<BB, LL>>>(radius, 0u, 2u);             // key(2) data = (0,2)
    k_out<<<(BB * LL + 255) / 256, 256>>>(out);
}